// round 12
// baseline (speedup 1.0000x reference)
#include <cuda_runtime.h>

// Scratch (no device allocation allowed -> __device__ globals)
__device__ float g_part[1024 * 2]; // partial maxes [B*16, C]
__device__ float g_M[2 * 64];      // fused weights W1@W2        [C, D2]
__device__ float g_c[64 * 64];     // per-batch fused bias       [B, D2]
__device__ int   g_cnt = 0;        // last-block ticket (self-resetting)

static const int B_ = 64;
static const int N_ = 32768;
static const int P1_GRID = 1024;        // 16 chunks per batch

// -------- Kernel 1: partial per-batch max + last-block prep (proven) ------
__global__ void __launch_bounds__(256)
max_prep_kernel(const float4* __restrict__ x,
                const float*  __restrict__ W1,
                const float*  __restrict__ b1,
                const float*  __restrict__ G1,
                const float*  __restrict__ W2,
                const float*  __restrict__ b2) {
    const int tid = threadIdx.x;
    const int blk = blockIdx.x;
    const float NEG_INF = __int_as_float(0xff800000);

    // ---- block partial max over its 16KB chunk ----
    {
        const long long base = (long long)blk * 1024;   // float4 index
        float m0 = NEG_INF, m1 = NEG_INF;
        #pragma unroll
        for (int j = 0; j < 4; j++) {
            float4 v = __ldg(&x[base + j * 256 + tid]);
            m0 = fmaxf(m0, fmaxf(v.x, v.z));
            m1 = fmaxf(m1, fmaxf(v.y, v.w));
        }
        #pragma unroll
        for (int o = 16; o > 0; o >>= 1) {
            m0 = fmaxf(m0, __shfl_xor_sync(0xffffffffu, m0, o));
            m1 = fmaxf(m1, __shfl_xor_sync(0xffffffffu, m1, o));
        }
        __shared__ float s0[8], s1[8];
        const int lane = tid & 31;
        const int w    = tid >> 5;
        if (lane == 0) { s0[w] = m0; s1[w] = m1; }
        __syncthreads();
        if (tid == 0) {
            float r0 = s0[0], r1 = s1[0];
            #pragma unroll
            for (int j = 1; j < 8; j++) {
                r0 = fmaxf(r0, s0[j]);
                r1 = fmaxf(r1, s1[j]);
            }
            g_part[blk * 2 + 0] = r0;
            g_part[blk * 2 + 1] = r1;
        }
    }

    // ---- elect last block ----
    __shared__ int isLast;
    __threadfence();
    if (tid == 0) {
        int t = atomicAdd(&g_cnt, 1);
        isLast = (t == P1_GRID - 1);
    }
    __syncthreads();
    if (!isLast) return;

    // ---- final reduce: beta[b][c] into shared ----
    __shared__ float sbeta[128];
    if (tid < 128) {
        const int bb = tid >> 1;
        const int ch = tid & 1;
        float m = NEG_INF;
        #pragma unroll
        for (int j = 0; j < 16; j++)
            m = fmaxf(m, g_part[(bb * 16 + j) * 2 + ch]);
        sbeta[tid] = m;
    }
    __syncthreads();

    // ---- g_M: threads 0..63, one output column each ----
    if (tid < 64) {
        const int d = tid;
        float a0 = 0.f, a1 = 0.f;
        #pragma unroll
        for (int k = 0; k < 32; k++) {
            const float w2kd = W2[k * 64 + d];
            a0 = fmaf(W1[k],      w2kd, a0);
            a1 = fmaf(W1[32 + k], w2kd, a1);
        }
        g_M[d]      = a0;
        g_M[64 + d] = a1;
    }

    // ---- g_c: 4096 outputs, 16 per thread, batch hoisted per thread ----
    {
        const int bb    = tid >> 2;        // 0..63
        const int dbase = (tid & 3) * 16;  // 0,16,32,48
        const float beta0 = sbeta[bb * 2 + 0];
        const float beta1 = sbeta[bb * 2 + 1];
        float wv[32];
        #pragma unroll
        for (int k = 0; k < 32; k++)
            wv[k] = b1[k] - beta0 * G1[k] - beta1 * G1[32 + k];
        #pragma unroll
        for (int i = 0; i < 16; i++) {
            const int d = dbase + i;
            float acc = b2[d];
            #pragma unroll
            for (int k = 0; k < 32; k++)
                acc = fmaf(wv[k], W2[k * 64 + d], acc);
            g_c[bb * 64 + d] = acc;
        }
    }

    // ---- reset ticket for next graph replay ----
    __syncthreads();
    if (tid == 0) atomicExch(&g_cnt, 0);
}

// 256-bit streaming store (sm_100a+/sm_103a): one STG.256, evict-first.
__device__ __forceinline__ void stcs_v8(float* p,
                                        float a0, float a1, float a2, float a3,
                                        float a4, float a5, float a6, float a7) {
    asm volatile("st.global.cs.v8.f32 [%0], {%1,%2,%3,%4,%5,%6,%7,%8};"
                 :: "l"(p), "f"(a0), "f"(a1), "f"(a2), "f"(a3),
                    "f"(a4), "f"(a5), "f"(a6), "f"(a7)
                 : "memory");
}

// -------- Kernel 2: streaming epilogue with STG.256 -----------------------
// 16384 blocks x 256 threads; block = 128 points in one batch (128 | 32768).
// Thread owns a fixed 32B slice of the 256B row: d8 = tid&7 (floats
// 8*d8..8*d8+7), point pl = tid>>3 (0..31), 4 points per thread. A warp's
// single store instruction covers 1024B contiguous.
__global__ void __launch_bounds__(256) main_kernel(const float2* __restrict__ x,
                                                   float* __restrict__ out) {
    const int tid = threadIdx.x;
    const int d8  = tid & 7;         // which 8-float slice of the 64-wide row
    const int pl  = tid >> 3;        // point within group (0..31)
    const int b   = blockIdx.x >> 8; // 256 blocks per batch

    // weight slices for this thread's 8 output columns
    const float4 m0a = ((const float4*)g_M)[d8 * 2 + 0];
    const float4 m0b = ((const float4*)g_M)[d8 * 2 + 1];
    const float4 m1a = ((const float4*)g_M)[16 + d8 * 2 + 0];
    const float4 m1b = ((const float4*)g_M)[16 + d8 * 2 + 1];
    const float4 cca = ((const float4*)g_c)[b * 16 + d8 * 2 + 0];
    const float4 ccb = ((const float4*)g_c)[b * 16 + d8 * 2 + 1];

    const long long p0 = (long long)blockIdx.x * 128 + pl;
    // out float index of this thread's slice for point p0:
    float* obase = out + (long long)blockIdx.x * 8192 + pl * 64 + d8 * 8;

    float2 xv[4];
    #pragma unroll
    for (int j = 0; j < 4; j++)
        xv[j] = __ldg(&x[p0 + j * 32]);

    #pragma unroll
    for (int j = 0; j < 4; j++) {
        const float xx = xv[j].x, xy = xv[j].y;
        float o0 = fmaf(xx, m0a.x, fmaf(xy, m1a.x, cca.x));
        float o1 = fmaf(xx, m0a.y, fmaf(xy, m1a.y, cca.y));
        float o2 = fmaf(xx, m0a.z, fmaf(xy, m1a.z, cca.z));
        float o3 = fmaf(xx, m0a.w, fmaf(xy, m1a.w, cca.w));
        float o4 = fmaf(xx, m0b.x, fmaf(xy, m1b.x, ccb.x));
        float o5 = fmaf(xx, m0b.y, fmaf(xy, m1b.y, ccb.y));
        float o6 = fmaf(xx, m0b.z, fmaf(xy, m1b.z, ccb.z));
        float o7 = fmaf(xx, m0b.w, fmaf(xy, m1b.w, ccb.w));
        stcs_v8(obase + j * 2048, o0, o1, o2, o3, o4, o5, o6, o7);
    }
}

extern "C" void kernel_launch(void* const* d_in, const int* in_sizes, int n_in,
                              void* d_out, int out_size) {
    const float* pd = (const float*)d_in[0];   // [64, 32768, 2]
    const float* W1 = (const float*)d_in[1];   // [2, 32]
    const float* b1 = (const float*)d_in[2];   // [32]
    const float* G1 = (const float*)d_in[3];   // [2, 32]
    const float* W2 = (const float*)d_in[4];   // [32, 64]
    const float* b2 = (const float*)d_in[5];   // [64]
    float* out = (float*)d_out;                // [64, 32768, 64]

    max_prep_kernel<<<P1_GRID, 256>>>((const float4*)pd, W1, b1, G1, W2, b2);

    const int blocks = B_ * N_ / 128;          // 16384 blocks, 128 points each
    main_kernel<<<blocks, 256>>>((const float2*)pd, (float*)d_out);
}

// round 14
// speedup vs baseline: 1.1665x; 1.1665x over previous
#include <cuda_runtime.h>

// Scratch (no device allocation allowed -> __device__ globals)
__device__ float g_part[1024 * 2]; // partial maxes [B*16, C]
__device__ float g_M[2 * 64];      // fused weights W1@W2        [C, D2]
__device__ float g_c[64 * 64];     // per-batch fused bias       [B, D2]
__device__ int   g_cnt = 0;        // last-block ticket (self-resetting)

static const int B_ = 64;
static const int N_ = 32768;
static const int P1_GRID = 1024;        // 16 chunks per batch

// -------- Kernel 1: partial per-batch max + last-block prep (proven) ------
// 1024 blocks x 256 threads; each block reduces 1024 float4 (16KB) with 4
// independent float4 loads per thread. The last block to finish (atomic
// ticket) does the final 16-way max reduce and computes g_c / g_M, then
// resets the ticket for graph replay.
__global__ void __launch_bounds__(256)
max_prep_kernel(const float4* __restrict__ x,
                const float*  __restrict__ W1,
                const float*  __restrict__ b1,
                const float*  __restrict__ G1,
                const float*  __restrict__ W2,
                const float*  __restrict__ b2) {
    const int tid = threadIdx.x;
    const int blk = blockIdx.x;
    const float NEG_INF = __int_as_float(0xff800000);

    // ---- block partial max over its 16KB chunk ----
    {
        const long long base = (long long)blk * 1024;   // float4 index
        float m0 = NEG_INF, m1 = NEG_INF;
        #pragma unroll
        for (int j = 0; j < 4; j++) {
            float4 v = __ldg(&x[base + j * 256 + tid]);
            m0 = fmaxf(m0, fmaxf(v.x, v.z));
            m1 = fmaxf(m1, fmaxf(v.y, v.w));
        }
        #pragma unroll
        for (int o = 16; o > 0; o >>= 1) {
            m0 = fmaxf(m0, __shfl_xor_sync(0xffffffffu, m0, o));
            m1 = fmaxf(m1, __shfl_xor_sync(0xffffffffu, m1, o));
        }
        __shared__ float s0[8], s1[8];
        const int lane = tid & 31;
        const int w    = tid >> 5;
        if (lane == 0) { s0[w] = m0; s1[w] = m1; }
        __syncthreads();
        if (tid == 0) {
            float r0 = s0[0], r1 = s1[0];
            #pragma unroll
            for (int j = 1; j < 8; j++) {
                r0 = fmaxf(r0, s0[j]);
                r1 = fmaxf(r1, s1[j]);
            }
            g_part[blk * 2 + 0] = r0;
            g_part[blk * 2 + 1] = r1;
        }
    }

    // ---- elect last block ----
    __shared__ int isLast;
    __threadfence();
    if (tid == 0) {
        int t = atomicAdd(&g_cnt, 1);
        isLast = (t == P1_GRID - 1);
    }
    __syncthreads();
    if (!isLast) return;

    // ---- final reduce: beta[b][c] into shared ----
    __shared__ float sbeta[128];
    if (tid < 128) {
        const int bb = tid >> 1;
        const int ch = tid & 1;
        float m = NEG_INF;
        #pragma unroll
        for (int j = 0; j < 16; j++)
            m = fmaxf(m, g_part[(bb * 16 + j) * 2 + ch]);
        sbeta[tid] = m;
    }
    __syncthreads();

    // ---- g_M: threads 0..63, one output column each ----
    if (tid < 64) {
        const int d = tid;
        float a0 = 0.f, a1 = 0.f;
        #pragma unroll
        for (int k = 0; k < 32; k++) {
            const float w2kd = W2[k * 64 + d];
            a0 = fmaf(W1[k],      w2kd, a0);
            a1 = fmaf(W1[32 + k], w2kd, a1);
        }
        g_M[d]      = a0;
        g_M[64 + d] = a1;
    }

    // ---- g_c: 4096 outputs, 16 per thread, batch hoisted per thread ----
    {
        const int bb    = tid >> 2;        // 0..63
        const int dbase = (tid & 3) * 16;  // 0,16,32,48
        const float beta0 = sbeta[bb * 2 + 0];
        const float beta1 = sbeta[bb * 2 + 1];
        float wv[32];
        #pragma unroll
        for (int k = 0; k < 32; k++)
            wv[k] = b1[k] - beta0 * G1[k] - beta1 * G1[32 + k];
        #pragma unroll
        for (int i = 0; i < 16; i++) {
            const int d = dbase + i;
            float acc = b2[d];
            #pragma unroll
            for (int k = 0; k < 32; k++)
                acc = fmaf(wv[k], W2[k * 64 + d], acc);
            g_c[bb * 64 + d] = acc;
        }
    }

    // ---- reset ticket for next graph replay ----
    __syncthreads();
    if (tid == 0) atomicExch(&g_cnt, 0);
}

// -------- Kernel 2: streaming epilogue: out[p, :] = x[p,:]@M + c[b,:] -----
// Proven best shape (32 regs, occ ~89%, DRAM 75-77%): 32768 blocks x 256
// threads; block = 64 points in one batch (64 | 32768); thread writes 4
// float4 with streaming (evict-first) stores at a fixed d4 column.
__global__ void __launch_bounds__(256) main_kernel(const float2* __restrict__ x,
                                                   float4* __restrict__ out) {
    const int tid = threadIdx.x;
    const int d4  = tid & 15;        // which float4 of the 64-wide row (fixed)
    const int pl  = tid >> 4;        // point within group (0..15)
    const int b   = blockIdx.x >> 9; // 512 blocks per batch

    const float4 m0 = ((const float4*)g_M)[d4];
    const float4 m1 = ((const float4*)g_M)[16 + d4];
    const float4 cc = ((const float4*)g_c)[b * 16 + d4];

    const long long p0    = (long long)blockIdx.x * 64 + pl;
    const long long obase = (long long)blockIdx.x * 1024 + tid;

    float2 xv[4];
    #pragma unroll
    for (int j = 0; j < 4; j++)
        xv[j] = __ldg(&x[p0 + j * 16]);

    #pragma unroll
    for (int j = 0; j < 4; j++) {
        float4 o;
        o.x = fmaf(xv[j].x, m0.x, fmaf(xv[j].y, m1.x, cc.x));
        o.y = fmaf(xv[j].x, m0.y, fmaf(xv[j].y, m1.y, cc.y));
        o.z = fmaf(xv[j].x, m0.z, fmaf(xv[j].y, m1.z, cc.z));
        o.w = fmaf(xv[j].x, m0.w, fmaf(xv[j].y, m1.w, cc.w));
        __stcs(&out[obase + j * 256], o);
    }
}

extern "C" void kernel_launch(void* const* d_in, const int* in_sizes, int n_in,
                              void* d_out, int out_size) {
    const float* pd = (const float*)d_in[0];   // [64, 32768, 2]
    const float* W1 = (const float*)d_in[1];   // [2, 32]
    const float* b1 = (const float*)d_in[2];   // [32]
    const float* G1 = (const float*)d_in[3];   // [2, 32]
    const float* W2 = (const float*)d_in[4];   // [32, 64]
    const float* b2 = (const float*)d_in[5];   // [64]
    float* out = (float*)d_out;                // [64, 32768, 64]

    max_prep_kernel<<<P1_GRID, 256>>>((const float4*)pd, W1, b1, G1, W2, b2);

    const int blocks = B_ * N_ / 64;           // 32768 blocks, 64 points each
    main_kernel<<<blocks, 256>>>((const float2*)pd, (float4*)out);
}

// round 15
// speedup vs baseline: 1.2657x; 1.0850x over previous
#include <cuda_runtime.h>

// Scratch (no device allocation allowed -> __device__ globals)
__device__ float2 g_part2[1024];   // partial maxes, one float2 per chunk block
__device__ float  g_M[2 * 64];     // fused weights W1@W2        [C, D2]
__device__ float  g_c[64 * 64];    // per-batch fused bias       [B, D2]
__device__ int    g_bcnt[64];      // per-batch chunk tickets (self-resetting)

static const int B_ = 64;
static const int N_ = 32768;
static const int P1_GRID = 1024;        // 16 chunks per batch

// -------- Kernel 1: partial per-batch max + per-batch finisher prep -------
// 1024 blocks x 256 threads; each block reduces 1024 float4 (16KB) with 4
// independent float4 loads per thread. The 16th chunk block of each batch
// (per-batch atomic ticket) reduces that batch's 16 partials and computes
// c[b,:]; block 0 computes g_M (no beta dependency). All counters
// self-reset so graph replays are deterministic.
__global__ void __launch_bounds__(256)
max_prep_kernel(const float4* __restrict__ x,
                const float*  __restrict__ W1,
                const float*  __restrict__ b1,
                const float*  __restrict__ G1,
                const float*  __restrict__ W2,
                const float*  __restrict__ b2) {
    const int tid = threadIdx.x;
    const int blk = blockIdx.x;
    const int bb  = blk >> 4;            // batch of this chunk
    const float NEG_INF = __int_as_float(0xff800000);

    // ---- block partial max over its 16KB chunk ----
    {
        const long long base = (long long)blk * 1024;   // float4 index
        float m0 = NEG_INF, m1 = NEG_INF;
        #pragma unroll
        for (int j = 0; j < 4; j++) {
            float4 v = __ldg(&x[base + j * 256 + tid]);
            m0 = fmaxf(m0, fmaxf(v.x, v.z));
            m1 = fmaxf(m1, fmaxf(v.y, v.w));
        }
        #pragma unroll
        for (int o = 16; o > 0; o >>= 1) {
            m0 = fmaxf(m0, __shfl_xor_sync(0xffffffffu, m0, o));
            m1 = fmaxf(m1, __shfl_xor_sync(0xffffffffu, m1, o));
        }
        __shared__ float s0[8], s1[8];
        const int lane = tid & 31;
        const int w    = tid >> 5;
        if (lane == 0) { s0[w] = m0; s1[w] = m1; }
        __syncthreads();
        if (tid == 0) {
            float r0 = s0[0], r1 = s1[0];
            #pragma unroll
            for (int j = 1; j < 8; j++) {
                r0 = fmaxf(r0, s0[j]);
                r1 = fmaxf(r1, s1[j]);
            }
            g_part2[blk] = make_float2(r0, r1);
        }
    }

    // ---- block 0: compute g_M (independent of any beta) ----
    if (blk == 0 && tid >= 64 && tid < 128) {
        const int d = tid - 64;
        float a0 = 0.f, a1 = 0.f;
        #pragma unroll
        for (int k = 0; k < 32; k++) {
            const float w2kd = W2[k * 64 + d];
            a0 = fmaf(W1[k],      w2kd, a0);   // W1[0,k]
            a1 = fmaf(W1[32 + k], w2kd, a1);   // W1[1,k]
        }
        g_M[d]      = a0;
        g_M[64 + d] = a1;
    }

    // ---- per-batch ticket: 16th chunk of this batch becomes finisher ----
    __shared__ int isLast;
    __threadfence();
    if (tid == 0) {
        int t = atomicAdd(&g_bcnt[bb], 1);
        isLast = (t == 15);
        if (isLast) atomicExch(&g_bcnt[bb], 0);   // reset for next replay
    }
    __syncthreads();
    if (!isLast) return;

    // ---- finisher: reduce this batch's 16 partials ----
    __shared__ float sb0, sb1;
    if (tid < 32) {
        float2 p = g_part2[bb * 16 + (tid & 15)];
        float m0 = p.x, m1 = p.y;
        #pragma unroll
        for (int o = 8; o > 0; o >>= 1) {
            m0 = fmaxf(m0, __shfl_xor_sync(0xffffffffu, m0, o));
            m1 = fmaxf(m1, __shfl_xor_sync(0xffffffffu, m1, o));
        }
        if (tid == 0) { sb0 = m0; sb1 = m1; }
    }
    __syncthreads();

    // ---- c[bb, d] for d = tid (threads 0..63) ----
    if (tid < 64) {
        const float beta0 = sb0;
        const float beta1 = sb1;
        const int d = tid;
        float acc = b2[d];
        #pragma unroll
        for (int k = 0; k < 32; k++) {
            const float wgt = b1[k] - beta0 * G1[k] - beta1 * G1[32 + k];
            acc = fmaf(wgt, W2[k * 64 + d], acc);
        }
        g_c[bb * 64 + d] = acc;
    }
}

// -------- Kernel 2: streaming epilogue: out[p, :] = x[p,:]@M + c[b,:] -----
// Proven best shape (32 regs, occ ~89%, write-ceiling DRAM%): 32768 blocks x
// 256 threads; block = 64 points in one batch (64 | 32768); thread writes 4
// float4 with streaming (evict-first) stores at a fixed d4 column.
__global__ void __launch_bounds__(256) main_kernel(const float2* __restrict__ x,
                                                   float4* __restrict__ out) {
    const int tid = threadIdx.x;
    const int d4  = tid & 15;        // which float4 of the 64-wide row (fixed)
    const int pl  = tid >> 4;        // point within group (0..15)
    const int b   = blockIdx.x >> 9; // 512 blocks per batch

    const float4 m0 = ((const float4*)g_M)[d4];
    const float4 m1 = ((const float4*)g_M)[16 + d4];
    const float4 cc = ((const float4*)g_c)[b * 16 + d4];

    const long long p0    = (long long)blockIdx.x * 64 + pl;
    const long long obase = (long long)blockIdx.x * 1024 + tid;

    float2 xv[4];
    #pragma unroll
    for (int j = 0; j < 4; j++)
        xv[j] = __ldg(&x[p0 + j * 16]);

    #pragma unroll
    for (int j = 0; j < 4; j++) {
        float4 o;
        o.x = fmaf(xv[j].x, m0.x, fmaf(xv[j].y, m1.x, cc.x));
        o.y = fmaf(xv[j].x, m0.y, fmaf(xv[j].y, m1.y, cc.y));
        o.z = fmaf(xv[j].x, m0.z, fmaf(xv[j].y, m1.z, cc.z));
        o.w = fmaf(xv[j].x, m0.w, fmaf(xv[j].y, m1.w, cc.w));
        __stcs(&out[obase + j * 256], o);
    }
}

extern "C" void kernel_launch(void* const* d_in, const int* in_sizes, int n_in,
                              void* d_out, int out_size) {
    const float* pd = (const float*)d_in[0];   // [64, 32768, 2]
    const float* W1 = (const float*)d_in[1];   // [2, 32]
    const float* b1 = (const float*)d_in[2];   // [32]
    const float* G1 = (const float*)d_in[3];   // [2, 32]
    const float* W2 = (const float*)d_in[4];   // [32, 64]
    const float* b2 = (const float*)d_in[5];   // [64]
    float* out = (float*)d_out;                // [64, 32768, 64]

    max_prep_kernel<<<P1_GRID, 256>>>((const float4*)pd, W1, b1, G1, W2, b2);

    const int blocks = B_ * N_ / 64;           // 32768 blocks, 64 points each
    main_kernel<<<blocks, 256>>>((const float2*)pd, (float4*)out);
}

// round 16
// speedup vs baseline: 1.2763x; 1.0083x over previous
#include <cuda_runtime.h>

// Scratch (no device allocation allowed -> __device__ globals)
__device__ float2 g_part2[1024];   // partial maxes, one float2 per chunk block
__device__ float  g_M[2 * 64];     // fused weights W1@W2        [C, D2]
__device__ float  g_c[64 * 64];    // per-batch fused bias       [B, D2]
__device__ int    g_bcnt[64];      // per-batch chunk tickets (self-resetting)

static const int B_ = 64;
static const int N_ = 32768;
static const int P1_GRID = 1024;        // 16 chunks per batch

// -------- Kernel 1: partial per-batch max + per-batch finisher prep -------
// (unchanged from the 81.3us best) 1024 blocks x 256 threads; 16th chunk of
// each batch (per-batch ticket) computes c[b,:]; block 0 computes g_M.
__global__ void __launch_bounds__(256)
max_prep_kernel(const float4* __restrict__ x,
                const float*  __restrict__ W1,
                const float*  __restrict__ b1,
                const float*  __restrict__ G1,
                const float*  __restrict__ W2,
                const float*  __restrict__ b2) {
    const int tid = threadIdx.x;
    const int blk = blockIdx.x;
    const int bb  = blk >> 4;            // batch of this chunk
    const float NEG_INF = __int_as_float(0xff800000);

    // ---- block partial max over its 16KB chunk ----
    {
        const long long base = (long long)blk * 1024;   // float4 index
        float m0 = NEG_INF, m1 = NEG_INF;
        #pragma unroll
        for (int j = 0; j < 4; j++) {
            float4 v = __ldg(&x[base + j * 256 + tid]);
            m0 = fmaxf(m0, fmaxf(v.x, v.z));
            m1 = fmaxf(m1, fmaxf(v.y, v.w));
        }
        #pragma unroll
        for (int o = 16; o > 0; o >>= 1) {
            m0 = fmaxf(m0, __shfl_xor_sync(0xffffffffu, m0, o));
            m1 = fmaxf(m1, __shfl_xor_sync(0xffffffffu, m1, o));
        }
        __shared__ float s0[8], s1[8];
        const int lane = tid & 31;
        const int w    = tid >> 5;
        if (lane == 0) { s0[w] = m0; s1[w] = m1; }
        __syncthreads();
        if (tid == 0) {
            float r0 = s0[0], r1 = s1[0];
            #pragma unroll
            for (int j = 1; j < 8; j++) {
                r0 = fmaxf(r0, s0[j]);
                r1 = fmaxf(r1, s1[j]);
            }
            g_part2[blk] = make_float2(r0, r1);
        }
    }

    // ---- block 0: compute g_M (independent of any beta) ----
    if (blk == 0 && tid >= 64 && tid < 128) {
        const int d = tid - 64;
        float a0 = 0.f, a1 = 0.f;
        #pragma unroll
        for (int k = 0; k < 32; k++) {
            const float w2kd = W2[k * 64 + d];
            a0 = fmaf(W1[k],      w2kd, a0);   // W1[0,k]
            a1 = fmaf(W1[32 + k], w2kd, a1);   // W1[1,k]
        }
        g_M[d]      = a0;
        g_M[64 + d] = a1;
    }

    // ---- per-batch ticket: 16th chunk of this batch becomes finisher ----
    __shared__ int isLast;
    __threadfence();
    if (tid == 0) {
        int t = atomicAdd(&g_bcnt[bb], 1);
        isLast = (t == 15);
        if (isLast) atomicExch(&g_bcnt[bb], 0);   // reset for next replay
    }
    __syncthreads();
    if (!isLast) return;

    // ---- finisher: reduce this batch's 16 partials ----
    __shared__ float sb0, sb1;
    if (tid < 32) {
        float2 p = g_part2[bb * 16 + (tid & 15)];
        float m0 = p.x, m1 = p.y;
        #pragma unroll
        for (int o = 8; o > 0; o >>= 1) {
            m0 = fmaxf(m0, __shfl_xor_sync(0xffffffffu, m0, o));
            m1 = fmaxf(m1, __shfl_xor_sync(0xffffffffu, m1, o));
        }
        if (tid == 0) { sb0 = m0; sb1 = m1; }
    }
    __syncthreads();

    // ---- c[bb, d] for d = tid (threads 0..63) ----
    if (tid < 64) {
        const float beta0 = sb0;
        const float beta1 = sb1;
        const int d = tid;
        float acc = b2[d];
        #pragma unroll
        for (int k = 0; k < 32; k++) {
            const float wgt = b1[k] - beta0 * G1[k] - beta1 * G1[32 + k];
            acc = fmaf(wgt, W2[k * 64 + d], acc);
        }
        g_c[bb * 64 + d] = acc;
    }
}

// -------- Kernel 2: streaming epilogue: out[p, :] = x[p,:]@M + c[b,:] -----
// Same proven per-thread body (fixed d4 column, 4 points, 4 float4 __stcs,
// 32 regs) but 512-thread blocks: 16384 blocks, 128 points each. Fewer
// block-dispatch events per byte; warp mapping/addresses unchanged.
__global__ void __launch_bounds__(512) main_kernel(const float2* __restrict__ x,
                                                   float4* __restrict__ out) {
    const int tid = threadIdx.x;     // 0..511
    const int d4  = tid & 15;        // which float4 of the 64-wide row (fixed)
    const int pl  = tid >> 4;        // point within group (0..31)
    const int b   = blockIdx.x >> 8; // 256 blocks per batch

    const float4 m0 = ((const float4*)g_M)[d4];
    const float4 m1 = ((const float4*)g_M)[16 + d4];
    const float4 cc = ((const float4*)g_c)[b * 16 + d4];

    // Each half of the block (pl 0..15 / 16..31) behaves exactly like one
    // 256-thread block of the proven shape, covering 64 consecutive points.
    const long long p0    = (long long)blockIdx.x * 128 + pl;
    const long long obase = (long long)blockIdx.x * 2048 + tid;

    float2 xv[4];
    #pragma unroll
    for (int j = 0; j < 4; j++)
        xv[j] = __ldg(&x[p0 + j * 32]);

    #pragma unroll
    for (int j = 0; j < 4; j++) {
        float4 o;
        o.x = fmaf(xv[j].x, m0.x, fmaf(xv[j].y, m1.x, cc.x));
        o.y = fmaf(xv[j].x, m0.y, fmaf(xv[j].y, m1.y, cc.y));
        o.z = fmaf(xv[j].x, m0.z, fmaf(xv[j].y, m1.z, cc.z));
        o.w = fmaf(xv[j].x, m0.w, fmaf(xv[j].y, m1.w, cc.w));
        __stcs(&out[obase + j * 512], o);
    }
}

extern "C" void kernel_launch(void* const* d_in, const int* in_sizes, int n_in,
                              void* d_out, int out_size) {
    const float* pd = (const float*)d_in[0];   // [64, 32768, 2]
    const float* W1 = (const float*)d_in[1];   // [2, 32]
    const float* b1 = (const float*)d_in[2];   // [32]
    const float* G1 = (const float*)d_in[3];   // [2, 32]
    const float* W2 = (const float*)d_in[4];   // [32, 64]
    const float* b2 = (const float*)d_in[5];   // [64]
    float* out = (float*)d_out;                // [64, 32768, 64]

    max_prep_kernel<<<P1_GRID, 256>>>((const float4*)pd, W1, b1, G1, W2, b2);

    const int blocks = B_ * N_ / 128;          // 16384 blocks, 128 points each
    main_kernel<<<blocks, 512>>>((const float2*)pd, (float4*)out);
}